// round 13
// baseline (speedup 1.0000x reference)
#include <cuda_runtime.h>
#include <cstdint>

#define NUM_HEADS 8
#define IN_BITS   64
#define N_STATE   256
#define N_OUT     64
#define K_CONN    8
#define HASH      65536
#define BATCH     128
#define T_STEPS   128
#define TOTAL_IN  320   // IN_BITS + N_STATE

#define PACK_BLOCKS   4096           // 16M floats / (256 thr * 16 floats)
#define WPREC_SPLIT   16             // step-groups of 8 per batch
#define WPREC_BLOCKS  (BATCH * WPREC_SPLIT)

// Bit-packed threshold table: bit = (state_mem[n][a] >= 0.5). 2 MB, L2-resident.
__device__ uint32_t g_state_bits[N_STATE * (HASH / 32)];
// Precomputed window contribution mod 2^16: [b][step][neuron]. 8 MB.
__device__ uint16_t g_wacc16[BATCH * T_STEPS * N_STATE];

// ---------------------------------------------------------------------------
// Fused prologue. Blocks [0, PACK_BLOCKS): bit-pack state_mem (HBM-bound,
// 16 independent LDGs per thread -> saturates HBM even at 4 blocks/SM).
// Blocks [PACK_BLOCKS, +WPREC_BLOCKS): window-contribution table (dp2a-bound,
// fine-split for occupancy) -- runs concurrently under the pack's HBM stream.
// ---------------------------------------------------------------------------
__global__ __launch_bounds__(256)
void fused_pre_kernel(const float* __restrict__ sm,
                      const int*   __restrict__ bits,
                      const int*   __restrict__ state_coeffs)
{
    const int t = threadIdx.x;

    if (blockIdx.x < PACK_BLOCKS) {
        const int lane = t & 31;
        const int gw   = blockIdx.x * 8 + (t >> 5);   // global warp id
        const size_t base = (size_t)gw * 512;         // 512 floats per warp
        float v[16];
        #pragma unroll
        for (int j = 0; j < 16; j++)                  // 16 independent loads
            v[j] = sm[base + (size_t)j * 32 + lane];
        #pragma unroll
        for (int j = 0; j < 16; j++) {
            uint32_t bm = __ballot_sync(0xFFFFFFFFu, v[j] >= 0.5f);
            if (lane == 0) g_state_bits[gw * 16 + j] = bm;
        }
        return;
    }

    // ---- window precompute: block -> (batch b, 8-step group q) ----
    __shared__ uint32_t ww[8 * 16];     // 8 windows expanded to bytes
    const int blk = blockIdx.x - PACK_BLOCKS;
    const int b   = blk >> 4;
    const int q   = blk & 15;

    const int4* bits4 = reinterpret_cast<const int4*>(
        bits + (size_t)b * (T_STEPS * IN_BITS)) + q * 8 * 16;
    if (t < 8 * 16) {
        int4 v = bits4[t];
        ww[t] = (uint32_t)(v.x & 1) | ((uint32_t)(v.y & 1) << 8)
              | ((uint32_t)(v.z & 1) << 16) | ((uint32_t)(v.w & 1) << 24);
    }

    // window coeffs of neuron t as u16 pairs for dp2a
    uint32_t w2[32];
    {
        const int4* crow = reinterpret_cast<const int4*>(state_coeffs + (size_t)t * TOTAL_IN);
        #pragma unroll
        for (int k = 0; k < 16; k++) {
            int4 v = crow[k];
            w2[2*k]   = (uint32_t)(v.x & 0xFFFF) | ((uint32_t)v.y << 16);
            w2[2*k+1] = (uint32_t)(v.z & 0xFFFF) | ((uint32_t)v.w << 16);
        }
    }
    __syncthreads();

    uint16_t* dst = g_wacc16 + ((size_t)b << 15) + ((q * 8) << 8) + t;
    #pragma unroll
    for (int s = 0; s < 8; s++) {
        const uint4* xv = reinterpret_cast<const uint4*>(ww + s * 16);
        uint32_t a0 = 0u, a1 = 0u, a2 = 0u, a3 = 0u;
        #pragma unroll
        for (int k = 0; k < 4; k++) {
            uint4 x = xv[k];
            a0 = __dp2a_lo(w2[8*k+0], x.x, a0); a0 = __dp2a_hi(w2[8*k+1], x.x, a0);
            a1 = __dp2a_lo(w2[8*k+2], x.y, a1); a1 = __dp2a_hi(w2[8*k+3], x.y, a1);
            a2 = __dp2a_lo(w2[8*k+4], x.z, a2); a2 = __dp2a_hi(w2[8*k+5], x.z, a2);
            a3 = __dp2a_lo(w2[8*k+6], x.w, a3); a3 = __dp2a_hi(w2[8*k+7], x.w, a3);
        }
        dst[s << 8] = (uint16_t)(((a0 + a1) + (a2 + a3)) & 0xFFFFu);
    }
}

// ---------------------------------------------------------------------------
// Main scan (unchanged; 86.6 us measured). One CTA per batch, 256 threads,
// thread t = neuron t. Per-batch wacc slab (64 KB u16) copied to dynamic
// smem once; per step: LDS.U16 + 128 dp2a + 1 L2 gather + byte store + 1 bar.
// ---------------------------------------------------------------------------
__global__ __launch_bounds__(256, 1)
void ram_scan_kernel(const int*   __restrict__ bits,          // (B, T*64)
                     const int*   __restrict__ state_coeffs,  // (256, 320)
                     const int*   __restrict__ head_conn,     // (8, 64, 8)
                     const int*   __restrict__ head_coeffs,   // (8, 64, 8)
                     const float* __restrict__ head_mem,      // (8, 64, 65536)
                     float*       __restrict__ out)           // (B, 64)
{
    extern __shared__ uint32_t dyn[];
    uint16_t* wacc_s = reinterpret_cast<uint16_t*>(dyn);      // 32768 u16 = 64 KB
    uint32_t* stbuf  = dyn + 16384;                           // [2][64] state words

    const int b = blockIdx.x;
    const int t = threadIdx.x;                                // neuron id

    // ---- copy wacc slab into smem (coalesced, 16 uint4 per thread) ----
    {
        const uint4* src = reinterpret_cast<const uint4*>(g_wacc16 + ((size_t)b << 15));
        uint4* dst = reinterpret_cast<uint4*>(wacc_s);
        #pragma unroll
        for (int i = 0; i < 16; i++) dst[t + 256 * i] = src[t + 256 * i];
    }
    if (t < 128) stbuf[t] = 0u;   // both state buffers zeroed

    // ---- state coefficients as u16 pairs for dp2a ----
    uint32_t c2[128];
    {
        const int4* crow = reinterpret_cast<const int4*>(state_coeffs + (size_t)t * TOTAL_IN);
        #pragma unroll
        for (int k = 0; k < 64; k++) {
            int4 v = crow[16 + k];
            c2[2*k]   = (uint32_t)(v.x & 0xFFFF) | ((uint32_t)v.y << 16);
            c2[2*k+1] = (uint32_t)(v.z & 0xFFFF) | ((uint32_t)v.w << 16);
        }
    }
    __syncthreads();   // wacc_s + stbuf ready

    const uint32_t* prow = g_state_bits + ((size_t)t << 11);   // 2048 words/row

    #pragma unroll 2
    for (int step = 0; step < T_STEPS; step++) {
        const int cur = step & 1, nxt = cur ^ 1;
        const uint4* st4 = reinterpret_cast<const uint4*>(stbuf + cur * 64);

        // window contribution: one LDS.U16 (conflict-free)
        const uint32_t wacc = wacc_s[(step << 8) + t];

        // state dot: 128 dp2a over 16 broadcast uint4, 4 accumulator chains
        uint32_t a0 = 0u, a1 = 0u, a2 = 0u, a3 = 0u;
        #pragma unroll
        for (int q = 0; q < 16; q++) {
            uint4 x = st4[q];
            a0 = __dp2a_lo(c2[8*q+0], x.x, a0); a0 = __dp2a_hi(c2[8*q+1], x.x, a0);
            a1 = __dp2a_lo(c2[8*q+2], x.y, a1); a1 = __dp2a_hi(c2[8*q+3], x.y, a1);
            a2 = __dp2a_lo(c2[8*q+4], x.z, a2); a2 = __dp2a_hi(c2[8*q+5], x.z, a2);
            a3 = __dp2a_lo(c2[8*q+6], x.w, a3); a3 = __dp2a_hi(c2[8*q+7], x.w, a3);
        }
        const uint32_t addr = ((a0 + a1) + (a2 + a3) + wacc) & 0xFFFFu;

        // random gather (L2-resident 2 MB table)
        const uint32_t wword = __ldg(prow + (addr >> 5));

        reinterpret_cast<uint8_t*>(stbuf + nxt * 64)[t] =
            (uint8_t)((wword >> (addr & 31u)) & 1u);
        __syncthreads();   // new state visible; old buffer free
    }

    // ---- Head readout (threads 0..63); T even -> final state in stbuf[0] ----
    if (t < N_OUT) {
        const uint8_t* state_b = reinterpret_cast<const uint8_t*>(stbuf);
        const int* lw = bits + (size_t)b * (T_STEPS * IN_BITS) + (T_STEPS * IN_BITS - 3);
        const int hidx = (lw[0] << 2) + (lw[1] << 1) + lw[2];    // 0..7
        const int o    = t;
        const int base = (hidx * N_OUT + o) * K_CONN;
        uint32_t addr = 0u;
        #pragma unroll
        for (int k = 0; k < K_CONN; k++) {
            int conn = __ldg(head_conn + base + k);
            uint32_t c = (uint32_t)__ldg(head_coeffs + base + k);
            addr += state_b[conn] ? c : 0u;
        }
        addr &= 0xFFFFu;
        out[(size_t)b * N_OUT + o] =
            __ldg(head_mem + (((size_t)(hidx * N_OUT + o)) << 16) + addr);
    }
}

extern "C" void kernel_launch(void* const* d_in, const int* in_sizes, int n_in,
                              void* d_out, int out_size)
{
    const int*   bits         = (const int*)  d_in[0];
    const int*   state_coeffs = (const int*)  d_in[1];
    const float* state_mem    = (const float*)d_in[2];
    const int*   head_conn    = (const int*)  d_in[3];
    const int*   head_coeffs  = (const int*)  d_in[4];
    const float* head_mem     = (const float*)d_in[5];
    float*       out          = (float*)      d_out;

    const int scan_smem = 64 * 1024 + 2 * 64 * 4 + 16;   // wacc slab + stbuf
    cudaFuncSetAttribute(ram_scan_kernel,
                         cudaFuncAttributeMaxDynamicSharedMemorySize, scan_smem);

    fused_pre_kernel<<<PACK_BLOCKS + WPREC_BLOCKS, 256>>>(state_mem, bits, state_coeffs);
    ram_scan_kernel<<<BATCH, 256, scan_smem>>>(bits, state_coeffs,
                                               head_conn, head_coeffs, head_mem, out);
}

// round 14
// speedup vs baseline: 1.1629x; 1.1629x over previous
#include <cuda_runtime.h>
#include <cstdint>

#define NUM_HEADS 8
#define IN_BITS   64
#define N_STATE   256
#define N_OUT     64
#define K_CONN    8
#define HASH      65536
#define BATCH     128
#define T_STEPS   128
#define TOTAL_IN  320   // IN_BITS + N_STATE

#define WPREC_BLOCKS  BATCH          // 1 long block per batch, FIRST in grid
#define PACK_BLOCKS   4096           // 16M floats / (256 thr * 16 floats)

// Bit-packed threshold table: bit = (state_mem[n][a] >= 0.5). 2 MB, L2-resident.
__device__ uint32_t g_state_bits[N_STATE * (HASH / 32)];
// Precomputed window contribution mod 2^16: [b][step][neuron]. 8 MB.
__device__ uint16_t g_wacc16[BATCH * T_STEPS * N_STATE];

// ---------------------------------------------------------------------------
// Fused prologue, overlap done right:
//  blocks [0, 128):      wprec -- one block per batch, thread = neuron,
//                        coeffs loaded ONCE, full 128-step dp2a loop (~10 us,
//                        fma-pipe-bound). Scheduled in wave 1 on 128 SMs.
//  blocks [128, +4096):  pack -- bit-pack state_mem 64 MB -> 2 MB. 16
//                        independent LDGs/thread, HBM-bound, ~9.5 us. Fills
//                        the remaining SMs and cycles as co-resident with
//                        wprec (disjoint pipes: LSU/HBM vs fma).
// ---------------------------------------------------------------------------
__global__ __launch_bounds__(256)
void fused_pre_kernel(const float* __restrict__ sm,
                      const int*   __restrict__ bits,
                      const int*   __restrict__ state_coeffs)
{
    const int t = threadIdx.x;

    if (blockIdx.x >= WPREC_BLOCKS) {
        // ---- pack path (no __syncthreads on this path) ----
        const int lane = t & 31;
        const int gw   = (blockIdx.x - WPREC_BLOCKS) * 8 + (t >> 5);
        const size_t base = (size_t)gw * 512;         // 512 floats per warp
        float v[16];
        #pragma unroll
        for (int j = 0; j < 16; j++)                  // 16 independent loads
            v[j] = sm[base + (size_t)j * 32 + lane];
        #pragma unroll
        for (int j = 0; j < 16; j++) {
            uint32_t bm = __ballot_sync(0xFFFFFFFFu, v[j] >= 0.5f);
            if (lane == 0) g_state_bits[gw * 16 + j] = bm;
        }
        return;
    }

    // ---- wprec path: block = batch, thread = neuron, all 128 steps ----
    __shared__ uint32_t ww[T_STEPS * 16];   // 8 KB: all windows as bytes
    const int b = blockIdx.x;

    const int4* bits4 = reinterpret_cast<const int4*>(bits + (size_t)b * (T_STEPS * IN_BITS));
    for (int w = t; w < T_STEPS * 16; w += 256) {
        int4 v = bits4[w];
        ww[w] = (uint32_t)(v.x & 1) | ((uint32_t)(v.y & 1) << 8)
              | ((uint32_t)(v.z & 1) << 16) | ((uint32_t)(v.w & 1) << 24);
    }

    // window coeffs of neuron t as u16 pairs for dp2a (loaded once)
    uint32_t w2[32];
    {
        const int4* crow = reinterpret_cast<const int4*>(state_coeffs + (size_t)t * TOTAL_IN);
        #pragma unroll
        for (int k = 0; k < 16; k++) {
            int4 v = crow[k];
            w2[2*k]   = (uint32_t)(v.x & 0xFFFF) | ((uint32_t)v.y << 16);
            w2[2*k+1] = (uint32_t)(v.z & 0xFFFF) | ((uint32_t)v.w << 16);
        }
    }
    __syncthreads();

    uint16_t* dst = g_wacc16 + ((size_t)b << 15) + t;
    #pragma unroll 2
    for (int s = 0; s < T_STEPS; s++) {
        const uint4* xv = reinterpret_cast<const uint4*>(ww + s * 16);
        uint32_t a0 = 0u, a1 = 0u, a2 = 0u, a3 = 0u;
        #pragma unroll
        for (int k = 0; k < 4; k++) {
            uint4 x = xv[k];
            a0 = __dp2a_lo(w2[8*k+0], x.x, a0); a0 = __dp2a_hi(w2[8*k+1], x.x, a0);
            a1 = __dp2a_lo(w2[8*k+2], x.y, a1); a1 = __dp2a_hi(w2[8*k+3], x.y, a1);
            a2 = __dp2a_lo(w2[8*k+4], x.z, a2); a2 = __dp2a_hi(w2[8*k+5], x.z, a2);
            a3 = __dp2a_lo(w2[8*k+6], x.w, a3); a3 = __dp2a_hi(w2[8*k+7], x.w, a3);
        }
        dst[s << 8] = (uint16_t)(((a0 + a1) + (a2 + a3)) & 0xFFFFu);
    }
}

// ---------------------------------------------------------------------------
// Main scan (unchanged; 87-90 us measured). One CTA per batch, 256 threads,
// thread t = neuron t. Per-batch wacc slab (64 KB u16) copied to dynamic
// smem once; per step: LDS.U16 + 128 dp2a + 1 L2 gather + byte store + 1 bar.
// ---------------------------------------------------------------------------
__global__ __launch_bounds__(256, 1)
void ram_scan_kernel(const int*   __restrict__ bits,          // (B, T*64)
                     const int*   __restrict__ state_coeffs,  // (256, 320)
                     const int*   __restrict__ head_conn,     // (8, 64, 8)
                     const int*   __restrict__ head_coeffs,   // (8, 64, 8)
                     const float* __restrict__ head_mem,      // (8, 64, 65536)
                     float*       __restrict__ out)           // (B, 64)
{
    extern __shared__ uint32_t dyn[];
    uint16_t* wacc_s = reinterpret_cast<uint16_t*>(dyn);      // 32768 u16 = 64 KB
    uint32_t* stbuf  = dyn + 16384;                           // [2][64] state words

    const int b = blockIdx.x;
    const int t = threadIdx.x;                                // neuron id

    // ---- copy wacc slab into smem (coalesced, 16 uint4 per thread) ----
    {
        const uint4* src = reinterpret_cast<const uint4*>(g_wacc16 + ((size_t)b << 15));
        uint4* dst = reinterpret_cast<uint4*>(wacc_s);
        #pragma unroll
        for (int i = 0; i < 16; i++) dst[t + 256 * i] = src[t + 256 * i];
    }
    if (t < 128) stbuf[t] = 0u;   // both state buffers zeroed

    // ---- state coefficients as u16 pairs for dp2a ----
    uint32_t c2[128];
    {
        const int4* crow = reinterpret_cast<const int4*>(state_coeffs + (size_t)t * TOTAL_IN);
        #pragma unroll
        for (int k = 0; k < 64; k++) {
            int4 v = crow[16 + k];
            c2[2*k]   = (uint32_t)(v.x & 0xFFFF) | ((uint32_t)v.y << 16);
            c2[2*k+1] = (uint32_t)(v.z & 0xFFFF) | ((uint32_t)v.w << 16);
        }
    }
    __syncthreads();   // wacc_s + stbuf ready

    const uint32_t* prow = g_state_bits + ((size_t)t << 11);   // 2048 words/row

    #pragma unroll 2
    for (int step = 0; step < T_STEPS; step++) {
        const int cur = step & 1, nxt = cur ^ 1;
        const uint4* st4 = reinterpret_cast<const uint4*>(stbuf + cur * 64);

        // window contribution: one LDS.U16 (conflict-free)
        const uint32_t wacc = wacc_s[(step << 8) + t];

        // state dot: 128 dp2a over 16 broadcast uint4, 4 accumulator chains
        uint32_t a0 = 0u, a1 = 0u, a2 = 0u, a3 = 0u;
        #pragma unroll
        for (int q = 0; q < 16; q++) {
            uint4 x = st4[q];
            a0 = __dp2a_lo(c2[8*q+0], x.x, a0); a0 = __dp2a_hi(c2[8*q+1], x.x, a0);
            a1 = __dp2a_lo(c2[8*q+2], x.y, a1); a1 = __dp2a_hi(c2[8*q+3], x.y, a1);
            a2 = __dp2a_lo(c2[8*q+4], x.z, a2); a2 = __dp2a_hi(c2[8*q+5], x.z, a2);
            a3 = __dp2a_lo(c2[8*q+6], x.w, a3); a3 = __dp2a_hi(c2[8*q+7], x.w, a3);
        }
        const uint32_t addr = ((a0 + a1) + (a2 + a3) + wacc) & 0xFFFFu;

        // random gather (L2-resident 2 MB table)
        const uint32_t wword = __ldg(prow + (addr >> 5));

        reinterpret_cast<uint8_t*>(stbuf + nxt * 64)[t] =
            (uint8_t)((wword >> (addr & 31u)) & 1u);
        __syncthreads();   // new state visible; old buffer free
    }

    // ---- Head readout (threads 0..63); T even -> final state in stbuf[0] ----
    if (t < N_OUT) {
        const uint8_t* state_b = reinterpret_cast<const uint8_t*>(stbuf);
        const int* lw = bits + (size_t)b * (T_STEPS * IN_BITS) + (T_STEPS * IN_BITS - 3);
        const int hidx = (lw[0] << 2) + (lw[1] << 1) + lw[2];    // 0..7
        const int o    = t;
        const int base = (hidx * N_OUT + o) * K_CONN;
        uint32_t addr = 0u;
        #pragma unroll
        for (int k = 0; k < K_CONN; k++) {
            int conn = __ldg(head_conn + base + k);
            uint32_t c = (uint32_t)__ldg(head_coeffs + base + k);
            addr += state_b[conn] ? c : 0u;
        }
        addr &= 0xFFFFu;
        out[(size_t)b * N_OUT + o] =
            __ldg(head_mem + (((size_t)(hidx * N_OUT + o)) << 16) + addr);
    }
}

extern "C" void kernel_launch(void* const* d_in, const int* in_sizes, int n_in,
                              void* d_out, int out_size)
{
    const int*   bits         = (const int*)  d_in[0];
    const int*   state_coeffs = (const int*)  d_in[1];
    const float* state_mem    = (const float*)d_in[2];
    const int*   head_conn    = (const int*)  d_in[3];
    const int*   head_coeffs  = (const int*)  d_in[4];
    const float* head_mem     = (const float*)d_in[5];
    float*       out          = (float*)      d_out;

    const int scan_smem = 64 * 1024 + 2 * 64 * 4 + 16;   // wacc slab + stbuf
    cudaFuncSetAttribute(ram_scan_kernel,
                         cudaFuncAttributeMaxDynamicSharedMemorySize, scan_smem);

    fused_pre_kernel<<<WPREC_BLOCKS + PACK_BLOCKS, 256>>>(state_mem, bits, state_coeffs);
    ram_scan_kernel<<<BATCH, 256, scan_smem>>>(bits, state_coeffs,
                                               head_conn, head_coeffs, head_mem, out);
}